// round 8
// baseline (speedup 1.0000x reference)
#include <cuda_runtime.h>
#include <cstdint>
#include <cstddef>

// x_{t+1} = x_t + 0.1*tanh([x_t,u_t]@W1 + b1)@W2 + b2
// B=1024, T=200, SD=64, CD=32, H=512.
// 128 persistent CTAs x 512 threads. CTA split into 2 DECOUPLED groups of
// 256 threads / 4 batch rows, each running its own rollout with named
// barriers (bar.sync 1/2). Groups interleave on SMSPs so barrier convoys in
// one group are hidden by the other. W1: 80 k in registers + 16 k in smem.
// W2 in smem. All math fma.rn.f32x2 with batch-row pairs in lanes.

typedef unsigned long long u64;

static constexpr int   TSTEPS = 200;
static constexpr int   SDIM   = 64;
static constexpr int   CDIM   = 32;
static constexpr int   HDIM   = 512;
static constexpr int   ROWS   = 8;
static constexpr int   NBLK   = 1024 / ROWS;   // 128
static constexpr int   NTHR   = 512;
static constexpr float DTC    = 0.1f;
static constexpr int   OSTRIDE = (TSTEPS + 1) * SDIM;
static constexpr int   KREG   = 80;            // W1 k-rows in registers
static constexpr int   KSM    = 16;            // W1 k-rows in smem

// smem layout (u64 units)
static constexpr int W2P_U = HDIM * 32;        // 16384: W2 rows as u64 pairs
static constexpr int W1S_U = KSM * 256;        //  4096: W1 k=80..95 as float2
static constexpr int IN_U  = 2 * 192;          //   384: in[g][k][rp]
static constexpr int H_U   = 2 * 1024;         //  2048: h[g][c][rp]
static constexpr int PS_U  = 2 * 8 * 130;      //  2080: psd[g][ks][j] padded
static constexpr int B2_U  = 64;
static constexpr size_t SMEM_BYTES =
    (size_t)(W2P_U + W1S_U + IN_U + H_U + PS_U + B2_U) * 8;  // 200,448 B

__device__ __forceinline__ u64 ffma2(u64 a, u64 b, u64 c) {
    u64 d;
    asm("fma.rn.f32x2 %0, %1, %2, %3;" : "=l"(d) : "l"(a), "l"(b), "l"(c));
    return d;
}
__device__ __forceinline__ u64 fadd2(u64 a, u64 b) {
    u64 d;
    asm("add.rn.f32x2 %0, %1, %2;" : "=l"(d) : "l"(a), "l"(b));
    return d;
}
__device__ __forceinline__ u64 pack2(float lo, float hi) {
    u64 d;
    asm("mov.b64 %0, {%1, %2};" : "=l"(d) : "r"(__float_as_int(lo)), "r"(__float_as_int(hi)));
    return d;
}
__device__ __forceinline__ u64 dupf(float f) {
    u64 d;
    asm("mov.b64 %0, {%1, %1};" : "=l"(d) : "r"(__float_as_int(f)));
    return d;
}
__device__ __forceinline__ float2 unpack2(u64 d) {
    int lo, hi;
    asm("mov.b64 {%0, %1}, %2;" : "=r"(lo), "=r"(hi) : "l"(d));
    return make_float2(__int_as_float(lo), __int_as_float(hi));
}
__device__ __forceinline__ float fast_tanh(float x) {
    float e = __expf(2.0f * x);
    return 1.0f - __fdividef(2.0f, e + 1.0f);
}
#define BARG(id) asm volatile("bar.sync %0, %1;" :: "r"(id), "r"(256) : "memory")

__global__ void __launch_bounds__(NTHR, 1)
rollout_kernel(const float* __restrict__ x0,
               const float* __restrict__ controls,
               const float* __restrict__ W1,
               const float* __restrict__ b1,
               const float* __restrict__ W2,
               const float* __restrict__ b2,
               float* __restrict__ out)
{
    extern __shared__ u64 sm[];
    u64*    W2p = sm;                          // [k][32] (raw W2 rows as u64)
    float2* w1s = (float2*)(sm + W2P_U);       // [k'][256]
    u64*    inb = sm + W2P_U + W1S_U;          // [g][k][rp]
    u64*    hb  = inb + IN_U;                  // [g][c][rp]
    u64*    psb = hb + H_U;                    // [g][ks][130]
    u64*    b2d = psb + PS_U;                  // dup'd b2

    const int tid  = threadIdx.x;
    const int lane = tid & 31;
    const int wid  = tid >> 5;
    const int b0   = blockIdx.x * ROWS;

    // group decomposition: SMSP = wid&3 gets 2 warps of each group
    const int g    = (wid >> 2) & 1;
    const int gw   = (wid & 3) | ((wid >> 3) << 2);   // warp idx in group 0..7
    const int T    = gw * 32 + lane;                  // thread idx in group
    const int rb   = b0 + 4 * g;                      // group's first row
    const int bar  = 1 + g;

    u64* in_g = inb + g * 192;
    u64* h_g  = hb  + g * 1024;
    u64* ps_g = psb + g * 1040;

    // ---- prologue ----
    {   // W2 raw copy (rows are 32 u64 pairs)
        const ulonglong2* src = (const ulonglong2*)W2;
        ulonglong2* dst = (ulonglong2*)W2p;
        #pragma unroll
        for (int i = tid; i < W2P_U / 2; i += NTHR) dst[i] = src[i];
    }
    {   // W1 tail k=80..95 into smem
        const float2* W1f2 = (const float2*)W1;   // [k][256]
        #pragma unroll
        for (int q = 0; q < KSM; ++q)
            w1s[q * 256 + tid % 256] = W1f2[(KREG + q) * 256 + (tid % 256)];
        // (two groups write same data twice; benign)
    }
    if (tid < SDIM) b2d[tid] = dupf(b2[tid]);

    // W1 head k=0..79 in registers (cols 2T, 2T+1)
    float2 wreg[KREG];
    {
        const float2* W1f2 = (const float2*)W1;
        #pragma unroll
        for (int k = 0; k < KREG; ++k) wreg[k] = W1f2[k * 256 + T];
    }
    float2 b1v = ((const float2*)b1)[T];
    const u64 b1d0 = dupf(b1v.x);
    const u64 b1d1 = dupf(b1v.y);
    const u64 dtdup = dupf(DTC);

    // stage x0 + u(0) (per group), emit states[:,0,:]
    if (T < 128) {
        int i = T >> 1, rp = T & 1;
        in_g[2 * i + rp] = pack2(x0[(rb + 2 * rp) * SDIM + i],
                                 x0[(rb + 2 * rp + 1) * SDIM + i]);
    }
    if (T < 64) {
        int j = T & 31, rp = T >> 5;
        in_g[2 * (SDIM + j) + rp] =
            pack2(controls[(size_t)(rb + 2 * rp) * TSTEPS * CDIM + j],
                  controls[(size_t)(rb + 2 * rp + 1) * TSTEPS * CDIM + j]);
    }
    {
        int r = tid >> 6, i = tid & 63;
        out[(size_t)(b0 + r) * OSTRIDE + i] = x0[(b0 + r) * SDIM + i];
    }
    __syncthreads();

    const int ksB = gw;            // phase-B k-strip (64 k)
    const int hT4 = 4 * T;         // h store base (cols 2T, 2T+1)

    for (int t = 0; t < TSTEPS; ++t) {
        // prefetch next-step controls
        float un0 = 0.0f, un1 = 0.0f;
        if (T < 64 && t + 1 < TSTEPS) {
            int j = T & 31, rp = T >> 5;
            un0 = controls[(size_t)(rb + 2 * rp) * TSTEPS * CDIM
                           + (size_t)(t + 1) * CDIM + j];
            un1 = controls[(size_t)(rb + 2 * rp + 1) * TSTEPS * CDIM
                           + (size_t)(t + 1) * CDIM + j];
        }

        // ---- Phase A: 2 cols x 2 row-pairs; W1 from regs (80k) + smem (16k) ----
        u64 a00 = b1d0, a01 = b1d0;   // col 2T,   rp0/rp1
        u64 a10 = b1d1, a11 = b1d1;   // col 2T+1, rp0/rp1
        #pragma unroll
        for (int k = 0; k < KREG; ++k) {
            ulonglong2 uu = *(const ulonglong2*)&in_g[2 * k];
            u64 w0 = dupf(wreg[k].x);
            u64 w1 = dupf(wreg[k].y);
            a00 = ffma2(uu.x, w0, a00);
            a01 = ffma2(uu.y, w0, a01);
            a10 = ffma2(uu.x, w1, a10);
            a11 = ffma2(uu.y, w1, a11);
        }
        #pragma unroll
        for (int q = 0; q < KSM; ++q) {
            ulonglong2 uu = *(const ulonglong2*)&in_g[2 * (KREG + q)];
            float2 wv = w1s[q * 256 + T];
            u64 w0 = dupf(wv.x);
            u64 w1 = dupf(wv.y);
            a00 = ffma2(uu.x, w0, a00);
            a01 = ffma2(uu.y, w0, a01);
            a10 = ffma2(uu.x, w1, a10);
            a11 = ffma2(uu.y, w1, a11);
        }
        {   // tanh + store h[c][rp]
            float2 f00 = unpack2(a00), f01 = unpack2(a01);
            float2 f10 = unpack2(a10), f11 = unpack2(a11);
            u64 h00 = pack2(fast_tanh(f00.x), fast_tanh(f00.y));
            u64 h01 = pack2(fast_tanh(f01.x), fast_tanh(f01.y));
            u64 h10 = pack2(fast_tanh(f10.x), fast_tanh(f10.y));
            u64 h11 = pack2(fast_tanh(f11.x), fast_tanh(f11.y));
            *(ulonglong2*)&h_g[hT4]     = make_ulonglong2(h00, h01);
            *(ulonglong2*)&h_g[hT4 + 2] = make_ulonglong2(h10, h11);
        }
        BARG(bar);

        // stage u(t+1) now (A reads of in_s are done for this step)
        if (T < 64 && t + 1 < TSTEPS) {
            int j = T & 31, rp = T >> 5;
            in_g[2 * (SDIM + j) + rp] = pack2(un0, un1);
        }

        // ---- Phase B: warp = 64-k strip; lane = i-pair (i=2lane,2lane+1) ----
        u64 c00 = 0, c01 = 0, c10 = 0, c11 = 0;   // [ii][rp]
        #pragma unroll 16
        for (int q = 0; q < 64; ++q) {
            const int k = ksB * 64 + q;
            ulonglong2 hh = *(const ulonglong2*)&h_g[2 * k];
            float2 wv = unpack2(W2p[k * 32 + lane]);
            u64 w0 = dupf(wv.x);
            u64 w1 = dupf(wv.y);
            c00 = ffma2(hh.x, w0, c00);
            c01 = ffma2(hh.y, w0, c01);
            c10 = ffma2(hh.x, w1, c10);
            c11 = ffma2(hh.y, w1, c11);
        }
        {
            u64* p = &ps_g[ksB * 130 + 4 * lane];
            *(ulonglong2*)(p)     = make_ulonglong2(c00, c01);
            *(ulonglong2*)(p + 2) = make_ulonglong2(c10, c11);
        }
        BARG(bar);

        // ---- Epilogue (T<128): reduce 8 strips, x update, store states ----
        if (T < 128) {
            const int ip = T >> 2, ii = (T >> 1) & 1, rp = T & 1;
            const int i = 2 * ip + ii;
            u64 s = ps_g[T];
            #pragma unroll
            for (int q = 1; q < 8; ++q) s = fadd2(s, ps_g[q * 130 + T]);
            s = fadd2(s, b2d[i]);
            u64 xn = ffma2(dtdup, s, in_g[2 * i + rp]);
            in_g[2 * i + rp] = xn;
            float2 xv = unpack2(xn);
            size_t so = (size_t)(t + 1) * SDIM + i;
            out[(size_t)(rb + 2 * rp) * OSTRIDE + so]     = xv.x;
            out[(size_t)(rb + 2 * rp + 1) * OSTRIDE + so] = xv.y;
        }
        BARG(bar);
    }
}

extern "C" void kernel_launch(void* const* d_in, const int* in_sizes, int n_in,
                              void* d_out, int out_size) {
    const float* x0       = (const float*)d_in[0];
    const float* controls = (const float*)d_in[1];
    const float* W1       = (const float*)d_in[2];
    const float* b1       = (const float*)d_in[3];
    const float* W2       = (const float*)d_in[4];
    const float* b2       = (const float*)d_in[5];
    float* out = (float*)d_out;

    static bool attr_set = false;
    if (!attr_set) {
        cudaFuncSetAttribute(rollout_kernel,
                             cudaFuncAttributeMaxDynamicSharedMemorySize,
                             (int)SMEM_BYTES);
        attr_set = true;
    }
    rollout_kernel<<<NBLK, NTHR, SMEM_BYTES>>>(x0, controls, W1, b1, W2, b2, out);
}

// round 9
// speedup vs baseline: 1.5631x; 1.5631x over previous
#include <cuda_runtime.h>
#include <cstdint>
#include <cstddef>

// x_{t+1} = x_t + 0.1*tanh([x_t,u_t]@W1 + b1)@W2 + b2
// B=1024, T=200, SD=64, CD=32, H=512.
// 128 persistent CTAs x 256 threads (2 warps/SMSP, high-reg regime).
// 8 batch rows packed as 4 f32x2 row-pairs. Thread owns H-cols (t, t+256):
// W1 read once per CTA (32 k in regs + 64 k streamed LDG). h stored as two
// row-pair-packed arrays (conflict-free STS/LDS.128). Phase B warp strips
// read only the warp's own phase-A output -> syncwarp between phases.

typedef unsigned long long u64;

static constexpr int   TSTEPS = 200;
static constexpr int   SDIM   = 64;
static constexpr int   CDIM   = 32;
static constexpr int   HDIM   = 512;
static constexpr int   ROWS   = 8;
static constexpr int   NBLK   = 1024 / ROWS;   // 128
static constexpr int   NTHR   = 256;
static constexpr float DTC    = 0.1f;
static constexpr int   OSTRIDE = (TSTEPS + 1) * SDIM;

static constexpr int W2P_U = HDIM * 32;       // 16384: W2 rows as u64 i-pairs
static constexpr int HA_U  = HDIM * 2;        //  1024: {rows01,rows23} per col
static constexpr int HB_U  = HDIM * 2;        //  1024: {rows45,rows67} per col
static constexpr int IN_U  = 96 * 4;          //   384: in[k][rp]
static constexpr int PS_U  = 8 * 258;         //  2064: psd[w][rp*64+i] padded
static constexpr int B2_U  = 64;
static constexpr size_t SMEM_BYTES =
    (size_t)(W2P_U + HA_U + HB_U + IN_U + PS_U + B2_U) * 8;  // 167,552 B

__device__ __forceinline__ u64 ffma2(u64 a, u64 b, u64 c) {
    u64 d;
    asm("fma.rn.f32x2 %0, %1, %2, %3;" : "=l"(d) : "l"(a), "l"(b), "l"(c));
    return d;
}
__device__ __forceinline__ u64 fadd2(u64 a, u64 b) {
    u64 d;
    asm("add.rn.f32x2 %0, %1, %2;" : "=l"(d) : "l"(a), "l"(b));
    return d;
}
__device__ __forceinline__ u64 pack2(float lo, float hi) {
    u64 d;
    asm("mov.b64 %0, {%1, %2};" : "=l"(d) : "r"(__float_as_int(lo)), "r"(__float_as_int(hi)));
    return d;
}
__device__ __forceinline__ u64 dupf(float f) {
    u64 d;
    asm("mov.b64 %0, {%1, %1};" : "=l"(d) : "r"(__float_as_int(f)));
    return d;
}
__device__ __forceinline__ float2 unpack2(u64 d) {
    int lo, hi;
    asm("mov.b64 {%0, %1}, %2;" : "=r"(lo), "=r"(hi) : "l"(d));
    return make_float2(__int_as_float(lo), __int_as_float(hi));
}
__device__ __forceinline__ u64 tanh2(u64 v) {
    float2 f = unpack2(v);
    float e0 = __expf(2.0f * f.x);
    float e1 = __expf(2.0f * f.y);
    return pack2(1.0f - __fdividef(2.0f, e0 + 1.0f),
                 1.0f - __fdividef(2.0f, e1 + 1.0f));
}

__global__ void __launch_bounds__(NTHR, 1)
rollout_kernel(const float* __restrict__ x0,
               const float* __restrict__ controls,
               const float* __restrict__ W1,
               const float* __restrict__ b1,
               const float* __restrict__ W2,
               const float* __restrict__ b2,
               float* __restrict__ out)
{
    extern __shared__ u64 sm[];
    u64* W2p  = sm;                 // [k][32] {W2[k][2i],W2[k][2i+1]}
    u64* hA   = W2p + W2P_U;        // [c*2+{0,1}] rows(01),(23)
    u64* hB   = hA + HA_U;          // [c*2+{0,1}] rows(45),(67)
    u64* in_s = hB + HB_U;          // [k*4+rp]
    u64* psd  = in_s + IN_U;        // [w][rp*64+i], stride 258
    u64* b2d  = psd + PS_U;

    const int tid  = threadIdx.x;
    const int lane = tid & 31;
    const int w    = tid >> 5;
    const int b0   = blockIdx.x * ROWS;

    // ---- prologue ----
    {
        const ulonglong2* src = (const ulonglong2*)W2;
        ulonglong2* dst = (ulonglong2*)W2p;
        #pragma unroll
        for (int i = tid; i < W2P_U / 2; i += NTHR) dst[i] = src[i];
    }
    if (tid < SDIM) b2d[tid] = dupf(b2[tid]);

    const u64 b1d0 = dupf(b1[tid]);
    const u64 b1d1 = dupf(b1[tid + 256]);
    const u64 dtdup = dupf(DTC);

    // persistent W1 k=0..31 for cols (tid, tid+256)
    float wp0[32], wp1[32];
    #pragma unroll
    for (int k = 0; k < 32; ++k) {
        wp0[k] = W1[k * HDIM + tid];
        wp1[k] = W1[k * HDIM + tid + 256];
    }
    // streamed W1 (k=32..95, 8 blocks of 8), double-buffered
    float wb0[2][8], wb1[2][8];
    #pragma unroll
    for (int j = 0; j < 8; ++j) {
        wb0[0][j] = W1[(32 + j) * HDIM + tid];
        wb1[0][j] = W1[(32 + j) * HDIM + tid + 256];
    }

    // stage x0, u(0); emit states[:,0,:]
    {
        int i = tid >> 2, rp = tid & 3;
        in_s[i * 4 + rp] = pack2(x0[(b0 + 2 * rp) * SDIM + i],
                                 x0[(b0 + 2 * rp + 1) * SDIM + i]);
    }
    if (tid < 128) {
        int j = lane, rp = tid >> 5;
        in_s[(SDIM + j) * 4 + rp] =
            pack2(controls[(size_t)(b0 + 2 * rp) * TSTEPS * CDIM + j],
                  controls[(size_t)(b0 + 2 * rp + 1) * TSTEPS * CDIM + j]);
    }
    {
        int r = tid >> 5;
        out[(size_t)(b0 + r) * OSTRIDE + lane]      = x0[(b0 + r) * SDIM + lane];
        out[(size_t)(b0 + r) * OSTRIDE + lane + 32] = x0[(b0 + r) * SDIM + lane + 32];
    }
    __syncthreads();

    const int kb1 = 32 * w;          // phase-B strip part 1 (cols of this warp)
    const int kb2 = 256 + 32 * w;    // part 2

    for (int t = 0; t < TSTEPS; ++t) {
        // prefetch next-step controls
        float un0 = 0.0f, un1 = 0.0f;
        if (tid < 128 && t + 1 < TSTEPS) {
            int rp = tid >> 5;
            un0 = controls[(size_t)(b0 + 2 * rp) * TSTEPS * CDIM
                           + (size_t)(t + 1) * CDIM + lane];
            un1 = controls[(size_t)(b0 + 2 * rp + 1) * TSTEPS * CDIM
                           + (size_t)(t + 1) * CDIM + lane];
        }

        // ---- Phase A: cols (tid, tid+256), 4 row-pairs each ----
        u64 a0[4], a1[4];
        a0[0] = b1d0; a0[1] = b1d0; a0[2] = b1d0; a0[3] = b1d0;
        a1[0] = b1d1; a1[1] = b1d1; a1[2] = b1d1; a1[3] = b1d1;
        #pragma unroll
        for (int k = 0; k < 32; ++k) {
            ulonglong2 uA = *(const ulonglong2*)&in_s[k * 4];
            ulonglong2 uB = *(const ulonglong2*)&in_s[k * 4 + 2];
            u64 w0 = dupf(wp0[k]);
            u64 w1 = dupf(wp1[k]);
            a0[0] = ffma2(uA.x, w0, a0[0]);
            a0[1] = ffma2(uA.y, w0, a0[1]);
            a0[2] = ffma2(uB.x, w0, a0[2]);
            a0[3] = ffma2(uB.y, w0, a0[3]);
            a1[0] = ffma2(uA.x, w1, a1[0]);
            a1[1] = ffma2(uA.y, w1, a1[1]);
            a1[2] = ffma2(uB.x, w1, a1[2]);
            a1[3] = ffma2(uB.y, w1, a1[3]);
        }
        #pragma unroll
        for (int blk = 0; blk < 8; ++blk) {
            const int cur = blk & 1;
            const int kn = 32 + 8 * ((blk + 1) & 7);   // wraps to 32 for next step
            #pragma unroll
            for (int j = 0; j < 8; ++j) {
                wb0[cur ^ 1][j] = W1[(kn + j) * HDIM + tid];
                wb1[cur ^ 1][j] = W1[(kn + j) * HDIM + tid + 256];
            }
            #pragma unroll
            for (int j = 0; j < 8; ++j) {
                const int k = 32 + 8 * blk + j;
                ulonglong2 uA = *(const ulonglong2*)&in_s[k * 4];
                ulonglong2 uB = *(const ulonglong2*)&in_s[k * 4 + 2];
                u64 w0 = dupf(wb0[cur][j]);
                u64 w1 = dupf(wb1[cur][j]);
                a0[0] = ffma2(uA.x, w0, a0[0]);
                a0[1] = ffma2(uA.y, w0, a0[1]);
                a0[2] = ffma2(uB.x, w0, a0[2]);
                a0[3] = ffma2(uB.y, w0, a0[3]);
                a1[0] = ffma2(uA.x, w1, a1[0]);
                a1[1] = ffma2(uA.y, w1, a1[1]);
                a1[2] = ffma2(uB.x, w1, a1[2]);
                a1[3] = ffma2(uB.y, w1, a1[3]);
            }
        }
        // tanh + conflict-free stores (lane-consecutive 16B)
        *(ulonglong2*)&hA[2 * tid]         = make_ulonglong2(tanh2(a0[0]), tanh2(a0[1]));
        *(ulonglong2*)&hB[2 * tid]         = make_ulonglong2(tanh2(a0[2]), tanh2(a0[3]));
        *(ulonglong2*)&hA[2 * (tid + 256)] = make_ulonglong2(tanh2(a1[0]), tanh2(a1[1]));
        *(ulonglong2*)&hB[2 * (tid + 256)] = make_ulonglong2(tanh2(a1[2]), tanh2(a1[3]));
        __syncwarp();   // phase B reads only this warp's own cols

        // ---- Phase B: 64 k (this warp's cols), lane i-pair (2l, 2l+1) ----
        u64 c0[4], c1[4];
        #pragma unroll
        for (int q = 0; q < 4; ++q) { c0[q] = 0ull; c1[q] = 0ull; }
        #pragma unroll 8
        for (int q = 0; q < 32; ++q) {
            const int k = kb1 + q;
            ulonglong2 ha = *(const ulonglong2*)&hA[2 * k];
            ulonglong2 hb = *(const ulonglong2*)&hB[2 * k];
            float2 wv = unpack2(W2p[k * 32 + lane]);
            u64 w0 = dupf(wv.x);
            u64 w1 = dupf(wv.y);
            c0[0] = ffma2(ha.x, w0, c0[0]);
            c0[1] = ffma2(ha.y, w0, c0[1]);
            c0[2] = ffma2(hb.x, w0, c0[2]);
            c0[3] = ffma2(hb.y, w0, c0[3]);
            c1[0] = ffma2(ha.x, w1, c1[0]);
            c1[1] = ffma2(ha.y, w1, c1[1]);
            c1[2] = ffma2(hb.x, w1, c1[2]);
            c1[3] = ffma2(hb.y, w1, c1[3]);
        }
        #pragma unroll 8
        for (int q = 0; q < 32; ++q) {
            const int k = kb2 + q;
            ulonglong2 ha = *(const ulonglong2*)&hA[2 * k];
            ulonglong2 hb = *(const ulonglong2*)&hB[2 * k];
            float2 wv = unpack2(W2p[k * 32 + lane]);
            u64 w0 = dupf(wv.x);
            u64 w1 = dupf(wv.y);
            c0[0] = ffma2(ha.x, w0, c0[0]);
            c0[1] = ffma2(ha.y, w0, c0[1]);
            c0[2] = ffma2(hb.x, w0, c0[2]);
            c0[3] = ffma2(hb.y, w0, c0[3]);
            c1[0] = ffma2(ha.x, w1, c1[0]);
            c1[1] = ffma2(ha.y, w1, c1[1]);
            c1[2] = ffma2(hb.x, w1, c1[2]);
            c1[3] = ffma2(hb.y, w1, c1[3]);
        }
        {   // psd[w][rp*64 + i]: lane stores i-pair as ulonglong2
            u64* p = &psd[w * 258 + 2 * lane];
            *(ulonglong2*)(p)       = make_ulonglong2(c0[0], c1[0]);
            *(ulonglong2*)(p + 64)  = make_ulonglong2(c0[1], c1[1]);
            *(ulonglong2*)(p + 128) = make_ulonglong2(c0[2], c1[2]);
            *(ulonglong2*)(p + 192) = make_ulonglong2(c0[3], c1[3]);
        }
        __syncthreads();

        // ---- Epilogue: 8-way reduce, x update, store states ----
        {
            const int rp = tid >> 6, i = tid & 63;
            u64 s = psd[rp * 64 + i];
            #pragma unroll
            for (int q = 1; q < 8; ++q)
                s = fadd2(s, psd[q * 258 + rp * 64 + i]);
            s = fadd2(s, b2d[i]);
            u64 xn = ffma2(dtdup, s, in_s[i * 4 + rp]);
            in_s[i * 4 + rp] = xn;
            float2 xv = unpack2(xn);
            size_t so = (size_t)(t + 1) * SDIM + i;
            out[(size_t)(b0 + 2 * rp) * OSTRIDE + so]     = xv.x;
            out[(size_t)(b0 + 2 * rp + 1) * OSTRIDE + so] = xv.y;
        }
        if (tid < 128 && t + 1 < TSTEPS) {
            int rp = tid >> 5;
            in_s[(SDIM + lane) * 4 + rp] = pack2(un0, un1);
        }
        __syncthreads();
    }
}

extern "C" void kernel_launch(void* const* d_in, const int* in_sizes, int n_in,
                              void* d_out, int out_size) {
    const float* x0       = (const float*)d_in[0];
    const float* controls = (const float*)d_in[1];
    const float* W1       = (const float*)d_in[2];
    const float* b1       = (const float*)d_in[3];
    const float* W2       = (const float*)d_in[4];
    const float* b2       = (const float*)d_in[5];
    float* out = (float*)d_out;

    static bool attr_set = false;
    if (!attr_set) {
        cudaFuncSetAttribute(rollout_kernel,
                             cudaFuncAttributeMaxDynamicSharedMemorySize,
                             (int)SMEM_BYTES);
        attr_set = true;
    }
    rollout_kernel<<<NBLK, NTHR, SMEM_BYTES>>>(x0, controls, W1, b1, W2, b2, out);
}

// round 10
// speedup vs baseline: 1.6440x; 1.0517x over previous
#include <cuda_runtime.h>
#include <cstdint>
#include <cstddef>

// x_{t+1} = x_t + 0.1*tanh([x_t,u_t]@W1 + b1)@W2 + b2
// B=1024, T=200, SD=64, CD=32, H=512.
// 128 persistent CTAs x 256 threads (2 warps/SMSP, high-reg regime).
// Thread owns H-cols (tid, tid+256); W1 read once per CTA (32 k persistent
// in regs + 64 k double-buffer streamed LDG). h in conflict-free row-pair
// arrays; phase B warp strips self-produced (syncwarp only). tanh via
// MUFU.TANH; phase B halves fused for 2x MLP.

typedef unsigned long long u64;

static constexpr int   TSTEPS = 200;
static constexpr int   SDIM   = 64;
static constexpr int   CDIM   = 32;
static constexpr int   HDIM   = 512;
static constexpr int   ROWS   = 8;
static constexpr int   NBLK   = 1024 / ROWS;   // 128
static constexpr int   NTHR   = 256;
static constexpr float DTC    = 0.1f;
static constexpr int   OSTRIDE = (TSTEPS + 1) * SDIM;

static constexpr int W2P_U = HDIM * 32;       // 16384: W2 rows as u64 i-pairs
static constexpr int HA_U  = HDIM * 2;        //  1024: {rows01,rows23} per col
static constexpr int HB_U  = HDIM * 2;        //  1024: {rows45,rows67} per col
static constexpr int IN_U  = 96 * 4;          //   384: in[k][rp]
static constexpr int PS_U  = 8 * 258;         //  2064: psd[w][rp*64+i] padded
static constexpr int B2_U  = 64;
static constexpr size_t SMEM_BYTES =
    (size_t)(W2P_U + HA_U + HB_U + IN_U + PS_U + B2_U) * 8;  // 167,552 B

__device__ __forceinline__ u64 ffma2(u64 a, u64 b, u64 c) {
    u64 d;
    asm("fma.rn.f32x2 %0, %1, %2, %3;" : "=l"(d) : "l"(a), "l"(b), "l"(c));
    return d;
}
__device__ __forceinline__ u64 fadd2(u64 a, u64 b) {
    u64 d;
    asm("add.rn.f32x2 %0, %1, %2;" : "=l"(d) : "l"(a), "l"(b));
    return d;
}
__device__ __forceinline__ u64 pack2(float lo, float hi) {
    u64 d;
    asm("mov.b64 %0, {%1, %2};" : "=l"(d) : "r"(__float_as_int(lo)), "r"(__float_as_int(hi)));
    return d;
}
__device__ __forceinline__ u64 dupf(float f) {
    u64 d;
    asm("mov.b64 %0, {%1, %1};" : "=l"(d) : "r"(__float_as_int(f)));
    return d;
}
__device__ __forceinline__ float2 unpack2(u64 d) {
    int lo, hi;
    asm("mov.b64 {%0, %1}, %2;" : "=r"(lo), "=r"(hi) : "l"(d));
    return make_float2(__int_as_float(lo), __int_as_float(hi));
}
__device__ __forceinline__ float tanh_fast(float x) {
    float y;
    asm("tanh.approx.f32 %0, %1;" : "=f"(y) : "f"(x));
    return y;
}
__device__ __forceinline__ u64 tanh2(u64 v) {
    float2 f = unpack2(v);
    return pack2(tanh_fast(f.x), tanh_fast(f.y));
}

__global__ void __launch_bounds__(NTHR, 1)
rollout_kernel(const float* __restrict__ x0,
               const float* __restrict__ controls,
               const float* __restrict__ W1,
               const float* __restrict__ b1,
               const float* __restrict__ W2,
               const float* __restrict__ b2,
               float* __restrict__ out)
{
    extern __shared__ u64 sm[];
    u64* W2p  = sm;                 // [k][32] {W2[k][2i],W2[k][2i+1]}
    u64* hA   = W2p + W2P_U;        // [c*2+{0,1}] rows(01),(23)
    u64* hB   = hA + HA_U;          // [c*2+{0,1}] rows(45),(67)
    u64* in_s = hB + HB_U;          // [k*4+rp]
    u64* psd  = in_s + IN_U;        // [w][rp*64+i], stride 258
    u64* b2d  = psd + PS_U;

    const int tid  = threadIdx.x;
    const int lane = tid & 31;
    const int w    = tid >> 5;
    const int b0   = blockIdx.x * ROWS;

    // ---- prologue ----
    {
        const ulonglong2* src = (const ulonglong2*)W2;
        ulonglong2* dst = (ulonglong2*)W2p;
        #pragma unroll
        for (int i = tid; i < W2P_U / 2; i += NTHR) dst[i] = src[i];
    }
    if (tid < SDIM) b2d[tid] = dupf(b2[tid]);

    const u64 b1d0 = dupf(b1[tid]);
    const u64 b1d1 = dupf(b1[tid + 256]);
    const u64 dtdup = dupf(DTC);

    // persistent W1 k=0..31 for cols (tid, tid+256)
    float wp0[32], wp1[32];
    #pragma unroll
    for (int k = 0; k < 32; ++k) {
        wp0[k] = W1[k * HDIM + tid];
        wp1[k] = W1[k * HDIM + tid + 256];
    }
    // streamed W1 (k=32..95, 8 blocks of 8), double-buffered
    float wb0[2][8], wb1[2][8];
    #pragma unroll
    for (int j = 0; j < 8; ++j) {
        wb0[0][j] = W1[(32 + j) * HDIM + tid];
        wb1[0][j] = W1[(32 + j) * HDIM + tid + 256];
    }

    // stage x0, u(0); emit states[:,0,:]
    {
        int i = tid >> 2, rp = tid & 3;
        in_s[i * 4 + rp] = pack2(x0[(b0 + 2 * rp) * SDIM + i],
                                 x0[(b0 + 2 * rp + 1) * SDIM + i]);
    }
    if (tid < 128) {
        int j = lane, rp = tid >> 5;
        in_s[(SDIM + j) * 4 + rp] =
            pack2(controls[(size_t)(b0 + 2 * rp) * TSTEPS * CDIM + j],
                  controls[(size_t)(b0 + 2 * rp + 1) * TSTEPS * CDIM + j]);
    }
    {
        int r = tid >> 5;
        out[(size_t)(b0 + r) * OSTRIDE + lane]      = x0[(b0 + r) * SDIM + lane];
        out[(size_t)(b0 + r) * OSTRIDE + lane + 32] = x0[(b0 + r) * SDIM + lane + 32];
    }
    __syncthreads();

    const int kb1 = 32 * w;          // phase-B strip part 1 (cols of this warp)
    const int kb2 = 256 + 32 * w;    // part 2

    for (int t = 0; t < TSTEPS; ++t) {
        // prefetch next-step controls
        float un0 = 0.0f, un1 = 0.0f;
        if (tid < 128 && t + 1 < TSTEPS) {
            int rp = tid >> 5;
            un0 = controls[(size_t)(b0 + 2 * rp) * TSTEPS * CDIM
                           + (size_t)(t + 1) * CDIM + lane];
            un1 = controls[(size_t)(b0 + 2 * rp + 1) * TSTEPS * CDIM
                           + (size_t)(t + 1) * CDIM + lane];
        }

        // ---- Phase A: cols (tid, tid+256), 4 row-pairs each ----
        u64 a0[4], a1[4];
        a0[0] = b1d0; a0[1] = b1d0; a0[2] = b1d0; a0[3] = b1d0;
        a1[0] = b1d1; a1[1] = b1d1; a1[2] = b1d1; a1[3] = b1d1;
        #pragma unroll
        for (int k = 0; k < 32; ++k) {
            ulonglong2 uA = *(const ulonglong2*)&in_s[k * 4];
            ulonglong2 uB = *(const ulonglong2*)&in_s[k * 4 + 2];
            u64 w0 = dupf(wp0[k]);
            u64 w1 = dupf(wp1[k]);
            a0[0] = ffma2(uA.x, w0, a0[0]);
            a0[1] = ffma2(uA.y, w0, a0[1]);
            a0[2] = ffma2(uB.x, w0, a0[2]);
            a0[3] = ffma2(uB.y, w0, a0[3]);
            a1[0] = ffma2(uA.x, w1, a1[0]);
            a1[1] = ffma2(uA.y, w1, a1[1]);
            a1[2] = ffma2(uB.x, w1, a1[2]);
            a1[3] = ffma2(uB.y, w1, a1[3]);
        }
        #pragma unroll
        for (int blk = 0; blk < 8; ++blk) {
            const int cur = blk & 1;
            const int kn = 32 + 8 * ((blk + 1) & 7);   // wraps to 32 for next step
            #pragma unroll
            for (int j = 0; j < 8; ++j) {
                wb0[cur ^ 1][j] = W1[(kn + j) * HDIM + tid];
                wb1[cur ^ 1][j] = W1[(kn + j) * HDIM + tid + 256];
            }
            #pragma unroll
            for (int j = 0; j < 8; ++j) {
                const int k = 32 + 8 * blk + j;
                ulonglong2 uA = *(const ulonglong2*)&in_s[k * 4];
                ulonglong2 uB = *(const ulonglong2*)&in_s[k * 4 + 2];
                u64 w0 = dupf(wb0[cur][j]);
                u64 w1 = dupf(wb1[cur][j]);
                a0[0] = ffma2(uA.x, w0, a0[0]);
                a0[1] = ffma2(uA.y, w0, a0[1]);
                a0[2] = ffma2(uB.x, w0, a0[2]);
                a0[3] = ffma2(uB.y, w0, a0[3]);
                a1[0] = ffma2(uA.x, w1, a1[0]);
                a1[1] = ffma2(uA.y, w1, a1[1]);
                a1[2] = ffma2(uB.x, w1, a1[2]);
                a1[3] = ffma2(uB.y, w1, a1[3]);
            }
        }
        // tanh (MUFU.TANH) + conflict-free stores (lane-consecutive 16B)
        *(ulonglong2*)&hA[2 * tid]         = make_ulonglong2(tanh2(a0[0]), tanh2(a0[1]));
        *(ulonglong2*)&hB[2 * tid]         = make_ulonglong2(tanh2(a0[2]), tanh2(a0[3]));
        *(ulonglong2*)&hA[2 * (tid + 256)] = make_ulonglong2(tanh2(a1[0]), tanh2(a1[1]));
        *(ulonglong2*)&hB[2 * (tid + 256)] = make_ulonglong2(tanh2(a1[2]), tanh2(a1[3]));
        __syncwarp();   // phase B reads only this warp's own cols

        // ---- Phase B: fused halves (kb1+q, kb2+q) for 2x MLP ----
        u64 c0[4], c1[4];
        #pragma unroll
        for (int q = 0; q < 4; ++q) { c0[q] = 0ull; c1[q] = 0ull; }
        #pragma unroll 8
        for (int q = 0; q < 32; ++q) {
            const int k1 = kb1 + q;
            const int k2 = kb2 + q;
            ulonglong2 ha1 = *(const ulonglong2*)&hA[2 * k1];
            ulonglong2 hb1 = *(const ulonglong2*)&hB[2 * k1];
            ulonglong2 ha2 = *(const ulonglong2*)&hA[2 * k2];
            ulonglong2 hb2 = *(const ulonglong2*)&hB[2 * k2];
            float2 wv1 = unpack2(W2p[k1 * 32 + lane]);
            float2 wv2 = unpack2(W2p[k2 * 32 + lane]);
            u64 p0 = dupf(wv1.x), p1 = dupf(wv1.y);
            u64 q0 = dupf(wv2.x), q1 = dupf(wv2.y);
            c0[0] = ffma2(ha1.x, p0, c0[0]);
            c0[1] = ffma2(ha1.y, p0, c0[1]);
            c0[2] = ffma2(hb1.x, p0, c0[2]);
            c0[3] = ffma2(hb1.y, p0, c0[3]);
            c1[0] = ffma2(ha1.x, p1, c1[0]);
            c1[1] = ffma2(ha1.y, p1, c1[1]);
            c1[2] = ffma2(hb1.x, p1, c1[2]);
            c1[3] = ffma2(hb1.y, p1, c1[3]);
            c0[0] = ffma2(ha2.x, q0, c0[0]);
            c0[1] = ffma2(ha2.y, q0, c0[1]);
            c0[2] = ffma2(hb2.x, q0, c0[2]);
            c0[3] = ffma2(hb2.y, q0, c0[3]);
            c1[0] = ffma2(ha2.x, q1, c1[0]);
            c1[1] = ffma2(ha2.y, q1, c1[1]);
            c1[2] = ffma2(hb2.x, q1, c1[2]);
            c1[3] = ffma2(hb2.y, q1, c1[3]);
        }
        {   // psd[w][rp*64 + i]: lane stores i-pair as ulonglong2
            u64* p = &psd[w * 258 + 2 * lane];
            *(ulonglong2*)(p)       = make_ulonglong2(c0[0], c1[0]);
            *(ulonglong2*)(p + 64)  = make_ulonglong2(c0[1], c1[1]);
            *(ulonglong2*)(p + 128) = make_ulonglong2(c0[2], c1[2]);
            *(ulonglong2*)(p + 192) = make_ulonglong2(c0[3], c1[3]);
        }
        __syncthreads();

        // ---- Epilogue: 8-way reduce, x update, store states ----
        {
            const int rp = tid >> 6, i = tid & 63;
            u64 s = psd[rp * 64 + i];
            #pragma unroll
            for (int q = 1; q < 8; ++q)
                s = fadd2(s, psd[q * 258 + rp * 64 + i]);
            s = fadd2(s, b2d[i]);
            u64 xn = ffma2(dtdup, s, in_s[i * 4 + rp]);
            in_s[i * 4 + rp] = xn;
            float2 xv = unpack2(xn);
            size_t so = (size_t)(t + 1) * SDIM + i;
            out[(size_t)(b0 + 2 * rp) * OSTRIDE + so]     = xv.x;
            out[(size_t)(b0 + 2 * rp + 1) * OSTRIDE + so] = xv.y;
        }
        if (tid < 128 && t + 1 < TSTEPS) {
            int rp = tid >> 5;
            in_s[(SDIM + lane) * 4 + rp] = pack2(un0, un1);
        }
        __syncthreads();
    }
}

extern "C" void kernel_launch(void* const* d_in, const int* in_sizes, int n_in,
                              void* d_out, int out_size) {
    const float* x0       = (const float*)d_in[0];
    const float* controls = (const float*)d_in[1];
    const float* W1       = (const float*)d_in[2];
    const float* b1       = (const float*)d_in[3];
    const float* W2       = (const float*)d_in[4];
    const float* b2       = (const float*)d_in[5];
    float* out = (float*)d_out;

    static bool attr_set = false;
    if (!attr_set) {
        cudaFuncSetAttribute(rollout_kernel,
                             cudaFuncAttributeMaxDynamicSharedMemorySize,
                             (int)SMEM_BYTES);
        attr_set = true;
    }
    rollout_kernel<<<NBLK, NTHR, SMEM_BYTES>>>(x0, controls, W1, b1, W2, b2, out);
}